// round 5
// baseline (speedup 1.0000x reference)
#include <cuda_runtime.h>
#include <cuda_bf16.h>
#include <cstdint>

// ---------------- problem constants ----------------
#define BATCH 8
#define SEQN  2048
#define HID   512
#define HD    64
#define CH    256
#define NCH   (SEQN / CH)          // 8
#define NROWS (BATCH * SEQN)       // 16384

// log2(0.96875) computed in double
#define LOG2G (-0.045803689613124966f)
// log2(10000)/32
#define L2_1E4_D32 (0.41524101186091903f)

// ---------------- scratch (static device memory; no allocations) ----------------
__device__ float g_Q[NROWS * HD];
__device__ float g_K[NROWS * HD];
__device__ float g_V[NROWS * HD];
__device__ float g_T[BATCH * NCH * HD * HD];   // per-chunk summaries
__device__ float g_S[BATCH * NCH * HD * HD];   // prefix states (exclusive)

// =====================================================================
// Kernel 1: fused projections + xPos
//   C[16384 x 64] = X[16384 x 512] @ W[512 x 64], then xpos (Q: up, K: down)
//   grid = (128, 3), block = 256. Tile: 128 rows x 64 cols, K-tile 32.
// =====================================================================
#define TM 128
#define KT 32
#define XS_STRIDE 132   // 16B-aligned rows (132 % 4 == 0) -> LDS.128 on 8-float reads

__global__ __launch_bounds__(256) void proj_kernel(
    const float* __restrict__ X,
    const float* __restrict__ Wq,
    const float* __restrict__ Wk,
    const float* __restrict__ Wv)
{
    __shared__ float Xs[KT][XS_STRIDE];   // transposed: Xs[k][row]
    __shared__ float Ws[KT][HD + 4];      // Ws[k][col], stride 68

    const int which = blockIdx.y;
    const float* __restrict__ W = (which == 0) ? Wq : (which == 1) ? Wk : Wv;
    float* __restrict__ Out = (which == 0) ? g_Q : (which == 1) ? g_K : g_V;

    const int row0 = blockIdx.x * TM;
    const int tid  = threadIdx.x;
    const int rg   = tid >> 4;     // 0..15 -> rows rg*8 .. rg*8+7
    const int cg   = tid & 15;     // 0..15 -> cols cg*4 .. cg*4+3

    float acc[8][4];
    #pragma unroll
    for (int i = 0; i < 8; i++)
        #pragma unroll
        for (int j = 0; j < 4; j++) acc[i][j] = 0.f;

    for (int kt = 0; kt < HID; kt += KT) {
        // load X tile (128 x 32) transposed into smem
        #pragma unroll
        for (int j = 0; j < 4; j++) {
            int fi = tid + j * 256;       // 0..1023 float4s
            int r  = fi >> 3;             // row 0..127
            int kq = fi & 7;              // which float4 in the 32-wide k strip
            float4 v = *(const float4*)&X[(row0 + r) * HID + kt + kq * 4];
            Xs[kq * 4 + 0][r] = v.x;
            Xs[kq * 4 + 1][r] = v.y;
            Xs[kq * 4 + 2][r] = v.z;
            Xs[kq * 4 + 3][r] = v.w;
        }
        // load W tile (32 x 64)
        #pragma unroll
        for (int j = 0; j < 2; j++) {
            int fi = tid + j * 256;       // 0..511 float4s
            int kk = fi >> 4;
            int cq = fi & 15;
            *(float4*)&Ws[kk][cq * 4] = *(const float4*)&W[(kt + kk) * HD + cq * 4];
        }
        __syncthreads();

        #pragma unroll 8
        for (int k = 0; k < KT; k++) {
            float a[8];
            #pragma unroll
            for (int i = 0; i < 8; i++) a[i] = Xs[k][rg * 8 + i];
            float4 bv = *(const float4*)&Ws[k][cg * 4];
            float b[4] = {bv.x, bv.y, bv.z, bv.w};
            #pragma unroll
            for (int i = 0; i < 8; i++)
                #pragma unroll
                for (int j = 0; j < 4; j++) acc[i][j] += a[i] * b[j];
        }
        __syncthreads();
    }

    // epilogue: xPos for Q (which==0) and K (which==1); V raw
    #pragma unroll
    for (int i = 0; i < 8; i++) {
        int r = row0 + rg * 8 + i;           // global row over B*SEQ
        int s = r & (SEQN - 1);              // position within sequence
        float* orow = &Out[r * HD + cg * 4];
        if (which < 2) {
            float y[4];
            #pragma unroll
            for (int pp = 0; pp < 2; pp++) {
                int c = (cg * 4) / 2 + pp;   // rotary pair index 0..31
                float sv = (2.f * c + 0.4f * HD) / (1.4f * HD);
                float ex = (float)s * (1.0f / 512.0f);
                if (which == 1) ex = -ex;    // downscale for K
                float sc = exp2f(log2f(sv) * ex);
                float invf = (float)exp2(-(double)c * (double)L2_1E4_D32);
                float ang = (float)s * invf;
                float cf = cosf(ang) * sc;
                float sf = sinf(ang) * sc;
                float x0 = acc[i][2 * pp], x1 = acc[i][2 * pp + 1];
                y[2 * pp]     = x0 * cf - x1 * sf;
                y[2 * pp + 1] = x1 * cf + x0 * sf;
            }
            float4 w4 = {y[0], y[1], y[2], y[3]};
            *(float4*)orow = w4;
        } else {
            float4 w4 = {acc[i][0], acc[i][1], acc[i][2], acc[i][3]};
            *(float4*)orow = w4;
        }
    }
}

// =====================================================================
// Kernel 2: per-chunk summaries T[b][c][a][v] = sum_k gamma^(256-k) K[k][a] V[k][v]
//   grid = 64 (b*8+c), block = 256
// =====================================================================
__global__ __launch_bounds__(256) void summary_kernel()
{
    const int bc = blockIdx.x;
    const int b = bc >> 3, c = bc & 7;
    const float* __restrict__ Kg = &g_K[(b * SEQN + c * CH) * HD];
    const float* __restrict__ Vg = &g_V[(b * SEQN + c * CH) * HD];

    __shared__ float Ks[64][HD + 4];
    __shared__ float Vs[64][HD + 4];

    const int tid = threadIdx.x;
    const int ag = tid >> 4;   // a rows ag*4..+3
    const int vg = tid & 15;   // v cols vg*4..+3

    float acc[4][4];
    #pragma unroll
    for (int i = 0; i < 4; i++)
        #pragma unroll
        for (int j = 0; j < 4; j++) acc[i][j] = 0.f;

    for (int k0 = 0; k0 < CH; k0 += 64) {
        #pragma unroll
        for (int j = 0; j < 4; j++) {
            int fi = tid + j * 256;
            int kk = fi >> 4;
            int cq = fi & 15;
            int kloc = k0 + kk;
            float w = exp2f(LOG2G * (float)(CH - kloc));
            float4 kv = *(const float4*)&Kg[kloc * HD + cq * 4];
            kv.x *= w; kv.y *= w; kv.z *= w; kv.w *= w;
            *(float4*)&Ks[kk][cq * 4] = kv;
            *(float4*)&Vs[kk][cq * 4] = *(const float4*)&Vg[kloc * HD + cq * 4];
        }
        __syncthreads();

        #pragma unroll 8
        for (int k = 0; k < 64; k++) {
            float4 av = *(const float4*)&Ks[k][ag * 4];
            float4 bv = *(const float4*)&Vs[k][vg * 4];
            float a[4] = {av.x, av.y, av.z, av.w};
            float bb[4] = {bv.x, bv.y, bv.z, bv.w};
            #pragma unroll
            for (int i = 0; i < 4; i++)
                #pragma unroll
                for (int j = 0; j < 4; j++) acc[i][j] += a[i] * bb[j];
        }
        __syncthreads();
    }

    float* __restrict__ T = &g_T[bc * HD * HD];
    #pragma unroll
    for (int i = 0; i < 4; i++) {
        float4 w4 = {acc[i][0], acc[i][1], acc[i][2], acc[i][3]};
        *(float4*)&T[(ag * 4 + i) * HD + vg * 4] = w4;
    }
}

// =====================================================================
// Kernel 3: exclusive scan over chunks: S_0 = 0; S_{c+1} = g^256 * S_c + T_c
//   grid = 8 (batch), block = 256, 16 elements per thread
// =====================================================================
__global__ __launch_bounds__(256) void scan_kernel()
{
    const int b = blockIdx.x;
    const int tid = threadIdx.x;
    const float G256 = exp2f(LOG2G * 256.f);

    float s[16];
    #pragma unroll
    for (int e = 0; e < 16; e++) s[e] = 0.f;

    for (int c = 0; c < NCH; c++) {
        float* __restrict__ S = &g_S[(b * NCH + c) * HD * HD];
        const float* __restrict__ T = &g_T[(b * NCH + c) * HD * HD];
        #pragma unroll
        for (int e = 0; e < 16; e++) {
            int idx = tid + e * 256;
            S[idx] = s[e];
            s[e] = G256 * s[e] + T[idx];
        }
    }
}

// =====================================================================
// Kernel 4: chunk attention
//   O[q] = gamma^q * Q_q @ S_c  +  sum over chunk keys of gamma^|q-k| (Q.K) V
//   grid = 128 (b,c,half), block = 256; 128 queries x 256 keys per block
// =====================================================================
#define QT 128
#define QS_STRIDE 132
// smem layout (floats):
//   Qs_t[64][132] | Pst[64][132] | Kst[64][68] | Vs[64][68] | Ss[64][68]
#define SM_QST 0
#define SM_PST (SM_QST + 64 * QS_STRIDE)
#define SM_KST (SM_PST + 64 * QS_STRIDE)
#define SM_VS  (SM_KST + 64 * 68)
#define SM_SS  (SM_VS  + 64 * 68)
#define ATT_SMEM_FLOATS (SM_SS + 64 * 68)
#define ATT_SMEM_BYTES  (ATT_SMEM_FLOATS * 4)

__global__ __launch_bounds__(256) void attend_kernel(float* __restrict__ out)
{
    extern __shared__ float sm[];
    float (*Qs_t)[QS_STRIDE] = (float(*)[QS_STRIDE])&sm[SM_QST];
    float (*Pst)[QS_STRIDE]  = (float(*)[QS_STRIDE])&sm[SM_PST];
    float (*Kst)[68]   = (float(*)[68]) &sm[SM_KST];
    float (*Vs)[68]    = (float(*)[68]) &sm[SM_VS];
    float (*Ss)[68]    = (float(*)[68]) &sm[SM_SS];

    const int bid  = blockIdx.x;
    const int half = bid & 1;
    const int c    = (bid >> 1) & 7;
    const int b    = bid >> 4;

    const float* __restrict__ Qg = &g_Q[(b * SEQN + c * CH + half * QT) * HD];
    const float* __restrict__ Kg = &g_K[(b * SEQN + c * CH) * HD];
    const float* __restrict__ Vg = &g_V[(b * SEQN + c * CH) * HD];
    const float* __restrict__ Sg = &g_S[(b * NCH + c) * HD * HD];

    const int tid = threadIdx.x;
    const int qg  = tid >> 4;    // q rows qg*8..+7
    const int xg  = tid & 15;    // 4-wide column group
    const int q0  = qg * 8;
    const int v0  = xg * 4;

    // load Q tile (128x64) transposed
    #pragma unroll
    for (int j = 0; j < 8; j++) {
        int fi = tid + j * 256;    // 0..2047 float4s
        int r  = fi >> 4;          // 0..127
        int cq = fi & 15;
        float4 v = *(const float4*)&Qg[r * HD + cq * 4];
        Qs_t[cq * 4 + 0][r] = v.x;
        Qs_t[cq * 4 + 1][r] = v.y;
        Qs_t[cq * 4 + 2][r] = v.z;
        Qs_t[cq * 4 + 3][r] = v.w;
    }
    // load state S (64x64)
    #pragma unroll
    for (int j = 0; j < 4; j++) {
        int fi = tid + j * 256;
        int r  = fi >> 4;
        int cq = fi & 15;
        *(float4*)&Ss[r][cq * 4] = *(const float4*)&Sg[r * HD + cq * 4];
    }
    __syncthreads();

    // init O with inter-chunk contribution: gamma^qloc * Q @ S
    float o[8][4];
    #pragma unroll
    for (int i = 0; i < 8; i++)
        #pragma unroll
        for (int j = 0; j < 4; j++) o[i][j] = 0.f;

    #pragma unroll 4
    for (int a = 0; a < HD; a++) {
        float qv[8];
        #pragma unroll
        for (int i = 0; i < 8; i++) qv[i] = Qs_t[a][q0 + i];
        float4 sv = *(const float4*)&Ss[a][v0];
        float s4[4] = {sv.x, sv.y, sv.z, sv.w};
        #pragma unroll
        for (int i = 0; i < 8; i++)
            #pragma unroll
            for (int j = 0; j < 4; j++) o[i][j] += qv[i] * s4[j];
    }
    #pragma unroll
    for (int i = 0; i < 8; i++) {
        float g = exp2f(LOG2G * (float)(half * QT + q0 + i));
        #pragma unroll
        for (int j = 0; j < 4; j++) o[i][j] *= g;
    }

    // intra-chunk: loop over 64-key tiles
    for (int kt = 0; kt < CH; kt += 64) {
        // load K tile (64x64, transposed) and V tile (64x64)
        #pragma unroll
        for (int j = 0; j < 4; j++) {
            int fi = tid + j * 256;
            int kk = fi >> 4;     // 0..63
            int cq = fi & 15;
            float4 kv = *(const float4*)&Kg[(kt + kk) * HD + cq * 4];
            Kst[cq * 4 + 0][kk] = kv.x;
            Kst[cq * 4 + 1][kk] = kv.y;
            Kst[cq * 4 + 2][kk] = kv.z;
            Kst[cq * 4 + 3][kk] = kv.w;
            *(float4*)&Vs[kk][cq * 4] = *(const float4*)&Vg[(kt + kk) * HD + cq * 4];
        }
        __syncthreads();

        // P[q][k] = Q.K (thread patch 8q x 4k)
        float p[8][4];
        #pragma unroll
        for (int i = 0; i < 8; i++)
            #pragma unroll
            for (int j = 0; j < 4; j++) p[i][j] = 0.f;

        #pragma unroll 4
        for (int a = 0; a < HD; a++) {
            float qv[8];
            #pragma unroll
            for (int i = 0; i < 8; i++) qv[i] = Qs_t[a][q0 + i];
            float4 kv = *(const float4*)&Kst[a][xg * 4];
            float k4[4] = {kv.x, kv.y, kv.z, kv.w};
            #pragma unroll
            for (int i = 0; i < 8; i++)
                #pragma unroll
                for (int j = 0; j < 4; j++) p[i][j] += qv[i] * k4[j];
        }
        // decay + store P transposed
        #pragma unroll
        for (int i = 0; i < 8; i++) {
            int gq = half * QT + q0 + i;
            #pragma unroll
            for (int j = 0; j < 4; j++) {
                int gk = kt + xg * 4 + j;
                float d = exp2f(LOG2G * fabsf((float)(gq - gk)));
                Pst[xg * 4 + j][q0 + i] = p[i][j] * d;
            }
        }
        __syncthreads();

        // O += P @ V (thread patch 8q x 4v)
        #pragma unroll 4
        for (int k = 0; k < 64; k++) {
            float pv[8];
            #pragma unroll
            for (int i = 0; i < 8; i++) pv[i] = Pst[k][q0 + i];
            float4 vv = *(const float4*)&Vs[k][v0];
            float v4[4] = {vv.x, vv.y, vv.z, vv.w};
            #pragma unroll
            for (int i = 0; i < 8; i++)
                #pragma unroll
                for (int j = 0; j < 4; j++) o[i][j] += pv[i] * v4[j];
        }
        __syncthreads();
    }

    // write output
    #pragma unroll
    for (int i = 0; i < 8; i++) {
        int row = b * SEQN + c * CH + half * QT + q0 + i;
        float4 w4 = {o[i][0], o[i][1], o[i][2], o[i][3]};
        *(float4*)&out[row * HD + v0] = w4;
    }
}

// =====================================================================
// launcher
// =====================================================================
extern "C" void kernel_launch(void* const* d_in, const int* in_sizes, int n_in,
                              void* d_out, int out_size)
{
    const float* X  = (const float*)d_in[0];
    const float* Wq = (const float*)d_in[1];
    const float* Wk = (const float*)d_in[2];
    const float* Wv = (const float*)d_in[3];
    float* out = (float*)d_out;

    cudaFuncSetAttribute(attend_kernel,
                         cudaFuncAttributeMaxDynamicSharedMemorySize,
                         ATT_SMEM_BYTES);

    proj_kernel<<<dim3(NROWS / TM, 3), 256>>>(X, Wq, Wk, Wv);
    summary_kernel<<<BATCH * NCH, 256>>>();
    scan_kernel<<<BATCH, 256>>>();
    attend_kernel<<<BATCH * NCH * 2, 256, ATT_SMEM_BYTES>>>(out);
}

// round 7
// speedup vs baseline: 1.1229x; 1.1229x over previous
#include <cuda_runtime.h>
#include <cuda_bf16.h>
#include <cstdint>

// ---------------- problem constants ----------------
#define BATCH 8
#define SEQN  2048
#define HID   512
#define HD    64
#define CH    256
#define NCH   (SEQN / CH)          // 8
#define NROWS (BATCH * SEQN)       // 16384

// log2(0.96875) computed in double
#define LOG2G (-0.045803689613124966f)
// log2(10000)/32
#define L2_1E4_D32 (0.41524101186091903f)

// ---------------- packed f32x2 helpers (sm_103a FFMA2 path) ----------------
__device__ __forceinline__ uint64_t pack2(float lo, float hi) {
    uint64_t r;
    asm("mov.b64 %0, {%1, %2};" : "=l"(r) : "f"(lo), "f"(hi));
    return r;
}
__device__ __forceinline__ float2 unpack2(uint64_t p) {
    float lo, hi;
    asm("mov.b64 {%0, %1}, %2;" : "=f"(lo), "=f"(hi) : "l"(p));
    return make_float2(lo, hi);
}
__device__ __forceinline__ void ffma2(uint64_t& d, uint64_t a, uint64_t b) {
    asm("fma.rn.f32x2 %0, %1, %2, %0;" : "+l"(d) : "l"(a), "l"(b));
}
__device__ __forceinline__ void fmul2(uint64_t& d, uint64_t a) {
    asm("mul.rn.f32x2 %0, %0, %1;" : "+l"(d) : "l"(a));
}

// ---------------- scratch (static device memory; no allocations) ----------------
__device__ float g_Q[NROWS * HD];
__device__ float g_K[NROWS * HD];
__device__ float g_V[NROWS * HD];
__device__ float g_T[BATCH * NCH * HD * HD];   // per-chunk summaries
__device__ float g_S[BATCH * NCH * HD * HD];   // prefix states (exclusive)

// =====================================================================
// Kernel 1: fused projections + xPos
//   C[16384 x 64] = X[16384 x 512] @ W[512 x 64], then xpos (Q: up, K: down)
//   grid = (128, 3), block = 256. Tile: 128 rows x 64 cols, K-tile 32.
//   Inner product uses packed f32x2 FMA: rows packed in pairs (contiguous in
//   smem -> free lane pairing), W broadcast operands replicated per lane.
// =====================================================================
#define TM 128
#define KT 32
#define XS_STRIDE 132   // 16B-aligned rows (132 % 4 == 0) -> LDS.128 on 8-float reads

__global__ __launch_bounds__(256) void proj_kernel(
    const float* __restrict__ X,
    const float* __restrict__ Wq,
    const float* __restrict__ Wk,
    const float* __restrict__ Wv)
{
    __shared__ float Xs[KT][XS_STRIDE];   // transposed: Xs[k][row]
    __shared__ float Ws[KT][HD + 4];      // Ws[k][col], stride 68

    const int which = blockIdx.y;
    const float* __restrict__ W = (which == 0) ? Wq : (which == 1) ? Wk : Wv;
    float* __restrict__ Out = (which == 0) ? g_Q : (which == 1) ? g_K : g_V;

    const int row0 = blockIdx.x * TM;
    const int tid  = threadIdx.x;
    const int rg   = tid >> 4;     // 0..15 -> rows rg*8 .. rg*8+7
    const int cg   = tid & 15;     // 0..15 -> cols cg*4 .. cg*4+3

    // packed accumulators: acc2[ip][j] holds rows (rg*8+2*ip, rg*8+2*ip+1), col cg*4+j
    uint64_t acc2[4][4];
    #pragma unroll
    for (int i = 0; i < 4; i++)
        #pragma unroll
        for (int j = 0; j < 4; j++) acc2[i][j] = 0ull;   // bits of (+0.f, +0.f)

    for (int kt = 0; kt < HID; kt += KT) {
        // load X tile (128 x 32) transposed into smem
        #pragma unroll
        for (int j = 0; j < 4; j++) {
            int fi = tid + j * 256;       // 0..1023 float4s
            int r  = fi >> 3;             // row 0..127
            int kq = fi & 7;              // which float4 in the 32-wide k strip
            float4 v = *(const float4*)&X[(row0 + r) * HID + kt + kq * 4];
            Xs[kq * 4 + 0][r] = v.x;
            Xs[kq * 4 + 1][r] = v.y;
            Xs[kq * 4 + 2][r] = v.z;
            Xs[kq * 4 + 3][r] = v.w;
        }
        // load W tile (32 x 64)
        #pragma unroll
        for (int j = 0; j < 2; j++) {
            int fi = tid + j * 256;       // 0..511 float4s
            int kk = fi >> 4;
            int cq = fi & 15;
            *(float4*)&Ws[kk][cq * 4] = *(const float4*)&W[(kt + kk) * HD + cq * 4];
        }
        __syncthreads();

        #pragma unroll 8
        for (int k = 0; k < KT; k++) {
            float4 alo = *(const float4*)&Xs[k][rg * 8];
            float4 ahi = *(const float4*)&Xs[k][rg * 8 + 4];
            uint64_t a2[4] = { pack2(alo.x, alo.y), pack2(alo.z, alo.w),
                               pack2(ahi.x, ahi.y), pack2(ahi.z, ahi.w) };
            float4 bv = *(const float4*)&Ws[k][cg * 4];
            uint64_t b2[4] = { pack2(bv.x, bv.x), pack2(bv.y, bv.y),
                               pack2(bv.z, bv.z), pack2(bv.w, bv.w) };
            #pragma unroll
            for (int ip = 0; ip < 4; ip++)
                #pragma unroll
                for (int j = 0; j < 4; j++) ffma2(acc2[ip][j], a2[ip], b2[j]);
        }
        __syncthreads();
    }

    // unpack accumulators
    float acc[8][4];
    #pragma unroll
    for (int ip = 0; ip < 4; ip++)
        #pragma unroll
        for (int j = 0; j < 4; j++) {
            float2 u = unpack2(acc2[ip][j]);
            acc[2 * ip][j]     = u.x;
            acc[2 * ip + 1][j] = u.y;
        }

    // epilogue: xPos for Q (which==0) and K (which==1); V raw
    #pragma unroll
    for (int i = 0; i < 8; i++) {
        int r = row0 + rg * 8 + i;           // global row over B*SEQ
        int s = r & (SEQN - 1);              // position within sequence
        float* orow = &Out[r * HD + cg * 4];
        if (which < 2) {
            float y[4];
            #pragma unroll
            for (int pp = 0; pp < 2; pp++) {
                int c = (cg * 4) / 2 + pp;   // rotary pair index 0..31
                float sv = (2.f * c + 0.4f * HD) / (1.4f * HD);
                float ex = (float)s * (1.0f / 512.0f);
                if (which == 1) ex = -ex;    // downscale for K
                float sc = exp2f(log2f(sv) * ex);
                float invf = (float)exp2(-(double)c * (double)L2_1E4_D32);
                float ang = (float)s * invf;
                float cf = cosf(ang) * sc;
                float sf = sinf(ang) * sc;
                float x0 = acc[i][2 * pp], x1 = acc[i][2 * pp + 1];
                y[2 * pp]     = x0 * cf - x1 * sf;
                y[2 * pp + 1] = x1 * cf + x0 * sf;
            }
            float4 w4 = {y[0], y[1], y[2], y[3]};
            *(float4*)orow = w4;
        } else {
            float4 w4 = {acc[i][0], acc[i][1], acc[i][2], acc[i][3]};
            *(float4*)orow = w4;
        }
    }
}

// =====================================================================
// Kernel 2: per-chunk summaries T[b][c][a][v] = sum_k gamma^(256-k) K[k][a] V[k][v]
//   grid = 64 (b*8+c), block = 256
// =====================================================================
__global__ __launch_bounds__(256) void summary_kernel()
{
    const int bc = blockIdx.x;
    const int b = bc >> 3, c = bc & 7;
    const float* __restrict__ Kg = &g_K[(b * SEQN + c * CH) * HD];
    const float* __restrict__ Vg = &g_V[(b * SEQN + c * CH) * HD];

    __shared__ float Ks[64][HD + 4];
    __shared__ float Vs[64][HD + 4];

    const int tid = threadIdx.x;
    const int ag = tid >> 4;   // a rows ag*4..+3
    const int vg = tid & 15;   // v cols vg*4..+3

    float acc[4][4];
    #pragma unroll
    for (int i = 0; i < 4; i++)
        #pragma unroll
        for (int j = 0; j < 4; j++) acc[i][j] = 0.f;

    for (int k0 = 0; k0 < CH; k0 += 64) {
        #pragma unroll
        for (int j = 0; j < 4; j++) {
            int fi = tid + j * 256;
            int kk = fi >> 4;
            int cq = fi & 15;
            int kloc = k0 + kk;
            float w = exp2f(LOG2G * (float)(CH - kloc));
            float4 kv = *(const float4*)&Kg[kloc * HD + cq * 4];
            kv.x *= w; kv.y *= w; kv.z *= w; kv.w *= w;
            *(float4*)&Ks[kk][cq * 4] = kv;
            *(float4*)&Vs[kk][cq * 4] = *(const float4*)&Vg[kloc * HD + cq * 4];
        }
        __syncthreads();

        #pragma unroll 8
        for (int k = 0; k < 64; k++) {
            float4 av = *(const float4*)&Ks[k][ag * 4];
            float4 bv = *(const float4*)&Vs[k][vg * 4];
            float a[4] = {av.x, av.y, av.z, av.w};
            float bb[4] = {bv.x, bv.y, bv.z, bv.w};
            #pragma unroll
            for (int i = 0; i < 4; i++)
                #pragma unroll
                for (int j = 0; j < 4; j++) acc[i][j] += a[i] * bb[j];
        }
        __syncthreads();
    }

    float* __restrict__ T = &g_T[bc * HD * HD];
    #pragma unroll
    for (int i = 0; i < 4; i++) {
        float4 w4 = {acc[i][0], acc[i][1], acc[i][2], acc[i][3]};
        *(float4*)&T[(ag * 4 + i) * HD + vg * 4] = w4;
    }
}

// =====================================================================
// Kernel 3: exclusive scan over chunks: S_0 = 0; S_{c+1} = g^256 * S_c + T_c
//   grid = 8 (batch), block = 256, 16 elements per thread
// =====================================================================
__global__ __launch_bounds__(256) void scan_kernel()
{
    const int b = blockIdx.x;
    const int tid = threadIdx.x;
    const float G256 = exp2f(LOG2G * 256.f);

    float s[16];
    #pragma unroll
    for (int e = 0; e < 16; e++) s[e] = 0.f;

    for (int c = 0; c < NCH; c++) {
        float* __restrict__ S = &g_S[(b * NCH + c) * HD * HD];
        const float* __restrict__ T = &g_T[(b * NCH + c) * HD * HD];
        #pragma unroll
        for (int e = 0; e < 16; e++) {
            int idx = tid + e * 256;
            S[idx] = s[e];
            s[e] = G256 * s[e] + T[idx];
        }
    }
}

// =====================================================================
// Kernel 4: chunk attention
//   O[q] = gamma^q * Q_q @ S_c  +  sum over chunk keys of gamma^|q-k| (Q.K) V
//   grid = 128 (b,c,half), block = 256; 128 queries x 256 keys per block
//   All three inner GEMM loops use packed f32x2 FMA (rows packed in pairs).
// =====================================================================
#define QT 128
#define QS_STRIDE 132
// smem layout (floats):
//   Qs_t[64][132] | Pst[64][132] | Kst[64][68] | Vs[64][68] | Ss[64][68]
#define SM_QST 0
#define SM_PST (SM_QST + 64 * QS_STRIDE)
#define SM_KST (SM_PST + 64 * QS_STRIDE)
#define SM_VS  (SM_KST + 64 * 68)
#define SM_SS  (SM_VS  + 64 * 68)
#define ATT_SMEM_FLOATS (SM_SS + 64 * 68)
#define ATT_SMEM_BYTES  (ATT_SMEM_FLOATS * 4)

__global__ __launch_bounds__(256) void attend_kernel(float* __restrict__ out)
{
    extern __shared__ float sm[];
    float (*Qs_t)[QS_STRIDE] = (float(*)[QS_STRIDE])&sm[SM_QST];
    float (*Pst)[QS_STRIDE]  = (float(*)[QS_STRIDE])&sm[SM_PST];
    float (*Kst)[68]   = (float(*)[68]) &sm[SM_KST];
    float (*Vs)[68]    = (float(*)[68]) &sm[SM_VS];
    float (*Ss)[68]    = (float(*)[68]) &sm[SM_SS];

    const int bid  = blockIdx.x;
    const int half = bid & 1;
    const int c    = (bid >> 1) & 7;
    const int b    = bid >> 4;

    const float* __restrict__ Qg = &g_Q[(b * SEQN + c * CH + half * QT) * HD];
    const float* __restrict__ Kg = &g_K[(b * SEQN + c * CH) * HD];
    const float* __restrict__ Vg = &g_V[(b * SEQN + c * CH) * HD];
    const float* __restrict__ Sg = &g_S[(b * NCH + c) * HD * HD];

    const int tid = threadIdx.x;
    const int qg  = tid >> 4;    // q rows qg*8..+7
    const int xg  = tid & 15;    // 4-wide column group
    const int q0  = qg * 8;
    const int v0  = xg * 4;

    // load Q tile (128x64) transposed
    #pragma unroll
    for (int j = 0; j < 8; j++) {
        int fi = tid + j * 256;    // 0..2047 float4s
        int r  = fi >> 4;          // 0..127
        int cq = fi & 15;
        float4 v = *(const float4*)&Qg[r * HD + cq * 4];
        Qs_t[cq * 4 + 0][r] = v.x;
        Qs_t[cq * 4 + 1][r] = v.y;
        Qs_t[cq * 4 + 2][r] = v.z;
        Qs_t[cq * 4 + 3][r] = v.w;
    }
    // load state S (64x64)
    #pragma unroll
    for (int j = 0; j < 4; j++) {
        int fi = tid + j * 256;
        int r  = fi >> 4;
        int cq = fi & 15;
        *(float4*)&Ss[r][cq * 4] = *(const float4*)&Sg[r * HD + cq * 4];
    }
    __syncthreads();

    // ---- inter-chunk: O = gamma^qloc * (Q @ S), packed over row pairs ----
    uint64_t o2[4][4];
    #pragma unroll
    for (int i = 0; i < 4; i++)
        #pragma unroll
        for (int j = 0; j < 4; j++) o2[i][j] = 0ull;

    #pragma unroll 4
    for (int a = 0; a < HD; a++) {
        float4 qlo = *(const float4*)&Qs_t[a][q0];
        float4 qhi = *(const float4*)&Qs_t[a][q0 + 4];
        uint64_t q2[4] = { pack2(qlo.x, qlo.y), pack2(qlo.z, qlo.w),
                           pack2(qhi.x, qhi.y), pack2(qhi.z, qhi.w) };
        float4 sv = *(const float4*)&Ss[a][v0];
        uint64_t s2[4] = { pack2(sv.x, sv.x), pack2(sv.y, sv.y),
                           pack2(sv.z, sv.z), pack2(sv.w, sv.w) };
        #pragma unroll
        for (int ip = 0; ip < 4; ip++)
            #pragma unroll
            for (int j = 0; j < 4; j++) ffma2(o2[ip][j], q2[ip], s2[j]);
    }
    // scale by gamma^qloc (per-row -> packed pair of scales)
    #pragma unroll
    for (int ip = 0; ip < 4; ip++) {
        float g0 = exp2f(LOG2G * (float)(half * QT + q0 + 2 * ip));
        float g1 = exp2f(LOG2G * (float)(half * QT + q0 + 2 * ip + 1));
        uint64_t gp = pack2(g0, g1);
        #pragma unroll
        for (int j = 0; j < 4; j++) fmul2(o2[ip][j], gp);
    }

    // intra-chunk: loop over 64-key tiles
    for (int kt = 0; kt < CH; kt += 64) {
        // load K tile (64x64, transposed) and V tile (64x64)
        #pragma unroll
        for (int j = 0; j < 4; j++) {
            int fi = tid + j * 256;
            int kk = fi >> 4;     // 0..63
            int cq = fi & 15;
            float4 kv = *(const float4*)&Kg[(kt + kk) * HD + cq * 4];
            Kst[cq * 4 + 0][kk] = kv.x;
            Kst[cq * 4 + 1][kk] = kv.y;
            Kst[cq * 4 + 2][kk] = kv.z;
            Kst[cq * 4 + 3][kk] = kv.w;
            *(float4*)&Vs[kk][cq * 4] = *(const float4*)&Vg[(kt + kk) * HD + cq * 4];
        }
        __syncthreads();

        // P[q][k] = Q.K — packed over row pairs
        uint64_t p2[4][4];
        #pragma unroll
        for (int i = 0; i < 4; i++)
            #pragma unroll
            for (int j = 0; j < 4; j++) p2[i][j] = 0ull;

        #pragma unroll 4
        for (int a = 0; a < HD; a++) {
            float4 qlo = *(const float4*)&Qs_t[a][q0];
            float4 qhi = *(const float4*)&Qs_t[a][q0 + 4];
            uint64_t q2[4] = { pack2(qlo.x, qlo.y), pack2(qlo.z, qlo.w),
                               pack2(qhi.x, qhi.y), pack2(qhi.z, qhi.w) };
            float4 kv = *(const float4*)&Kst[a][xg * 4];
            uint64_t k2[4] = { pack2(kv.x, kv.x), pack2(kv.y, kv.y),
                               pack2(kv.z, kv.z), pack2(kv.w, kv.w) };
            #pragma unroll
            for (int ip = 0; ip < 4; ip++)
                #pragma unroll
                for (int j = 0; j < 4; j++) ffma2(p2[ip][j], q2[ip], k2[j]);
        }
        // decay + store P transposed
        #pragma unroll
        for (int ip = 0; ip < 4; ip++) {
            int gq0 = half * QT + q0 + 2 * ip;
            #pragma unroll
            for (int j = 0; j < 4; j++) {
                int gk = kt + xg * 4 + j;
                float2 u = unpack2(p2[ip][j]);
                float d0 = exp2f(LOG2G * fabsf((float)(gq0 - gk)));
                float d1 = exp2f(LOG2G * fabsf((float)(gq0 + 1 - gk)));
                Pst[xg * 4 + j][q0 + 2 * ip]     = u.x * d0;
                Pst[xg * 4 + j][q0 + 2 * ip + 1] = u.y * d1;
            }
        }
        __syncthreads();

        // O += P @ V — packed over row pairs
        #pragma unroll 4
        for (int k = 0; k < 64; k++) {
            float4 plo = *(const float4*)&Pst[k][q0];
            float4 phi = *(const float4*)&Pst[k][q0 + 4];
            uint64_t pv2[4] = { pack2(plo.x, plo.y), pack2(plo.z, plo.w),
                                pack2(phi.x, phi.y), pack2(phi.z, phi.w) };
            float4 vv = *(const float4*)&Vs[k][v0];
            uint64_t v2[4] = { pack2(vv.x, vv.x), pack2(vv.y, vv.y),
                               pack2(vv.z, vv.z), pack2(vv.w, vv.w) };
            #pragma unroll
            for (int ip = 0; ip < 4; ip++)
                #pragma unroll
                for (int j = 0; j < 4; j++) ffma2(o2[ip][j], pv2[ip], v2[j]);
        }
        __syncthreads();
    }

    // write output (unpack row pairs)
    #pragma unroll
    for (int ip = 0; ip < 4; ip++) {
        float2 u0 = unpack2(o2[ip][0]);
        float2 u1 = unpack2(o2[ip][1]);
        float2 u2 = unpack2(o2[ip][2]);
        float2 u3 = unpack2(o2[ip][3]);
        int row0g = b * SEQN + c * CH + half * QT + q0 + 2 * ip;
        float4 w0 = {u0.x, u1.x, u2.x, u3.x};
        float4 w1 = {u0.y, u1.y, u2.y, u3.y};
        *(float4*)&out[row0g * HD + v0]       = w0;
        *(float4*)&out[(row0g + 1) * HD + v0] = w1;
    }
}

// =====================================================================
// launcher
// =====================================================================
extern "C" void kernel_launch(void* const* d_in, const int* in_sizes, int n_in,
                              void* d_out, int out_size)
{
    const float* X  = (const float*)d_in[0];
    const float* Wq = (const float*)d_in[1];
    const float* Wk = (const float*)d_in[2];
    const float* Wv = (const float*)d_in[3];
    float* out = (float*)d_out;

    cudaFuncSetAttribute(attend_kernel,
                         cudaFuncAttributeMaxDynamicSharedMemorySize,
                         ATT_SMEM_BYTES);

    proj_kernel<<<dim3(NROWS / TM, 3), 256>>>(X, Wq, Wk, Wv);
    summary_kernel<<<BATCH * NCH, 256>>>();
    scan_kernel<<<BATCH, 256>>>();
    attend_kernel<<<BATCH * NCH * 2, 256, ATT_SMEM_BYTES>>>(out);
}